// round 2
// baseline (speedup 1.0000x reference)
#include <cuda_runtime.h>
#include <cuda_bf16.h>

// Backflow: out[b,i,:] = 0.8 * sum_j exp(-|x_i-x_j|/3) * (x_i - x_j)
// (diagonal j==i contributes exactly 0 with plain differences, matching the
//  reference's eye()-injection + subtraction which cancels identically.)

#define N_PART 1024
#define TILE   256   // i-particles per CTA (== blockDim.x)

// -log2(e)/3 : exp(-d/3) == exp2(d * KEXP)
#define KEXP  (-0.48089834696298783f)

__device__ __forceinline__ float fast_sqrt(float x) {
    float r;
    asm("sqrt.approx.f32 %0, %1;" : "=f"(r) : "f"(x));
    return r;
}
__device__ __forceinline__ float fast_ex2(float x) {
    float r;
    asm("ex2.approx.f32 %0, %1;" : "=f"(r) : "f"(x));
    return r;
}

__global__ __launch_bounds__(TILE) void backflow_kernel(
    const float* __restrict__ x, float* __restrict__ out)
{
    __shared__ float sx[N_PART];
    __shared__ float sy[N_PART];
    __shared__ float sz[N_PART];

    const int b    = blockIdx.y;           // batch
    const int tile = blockIdx.x;           // i-tile
    const int tid  = threadIdx.x;

    const float* __restrict__ xb = x + (size_t)b * (N_PART * 3);

    // Cooperative, coalesced load of the whole batch row, de-interleaved
    // into sx/sy/sz so the inner loop does pure broadcast LDS.32.
    #pragma unroll
    for (int k = tid; k < 3 * N_PART; k += TILE) {
        float v = xb[k];
        int   p = k / 3;
        int   c = k - 3 * p;
        if (c == 0)      sx[p] = v;
        else if (c == 1) sy[p] = v;
        else             sz[p] = v;
    }
    __syncthreads();

    const int i = tile * TILE + tid;
    const float xi = sx[i];
    const float yi = sy[i];
    const float zi = sz[i];

    float ax = 0.f, ay = 0.f, az = 0.f;

    #pragma unroll 16
    for (int j = 0; j < N_PART; ++j) {
        const float dx = xi - sx[j];
        const float dy = yi - sy[j];
        const float dz = zi - sz[j];
        const float d2 = fmaf(dx, dx, fmaf(dy, dy, dz * dz));
        const float d  = fast_sqrt(d2);          // d=0 at j==i -> term is 0
        const float e  = fast_ex2(d * KEXP);     // exp(-d/3)
        ax = fmaf(e, dx, ax);
        ay = fmaf(e, dy, ay);
        az = fmaf(e, dz, az);
    }

    float* __restrict__ ob = out + (size_t)b * (N_PART * 3) + 3 * i;
    ob[0] = 0.8f * ax;
    ob[1] = 0.8f * ay;
    ob[2] = 0.8f * az;
}

extern "C" void kernel_launch(void* const* d_in, const int* in_sizes, int n_in,
                              void* d_out, int out_size)
{
    const float* x = (const float*)d_in[0];
    float* out = (float*)d_out;

    int B = in_sizes[0] / (N_PART * 3);   // 64 for the given shapes
    if (B < 1) B = 1;

    dim3 grid(N_PART / TILE, B);   // (4, 64) = 256 CTAs
    dim3 block(TILE);
    backflow_kernel<<<grid, block>>>(x, out);
}

// round 3
// speedup vs baseline: 1.0167x; 1.0167x over previous
#include <cuda_runtime.h>
#include <cuda_bf16.h>

// Backflow: out[b,i,:] = 0.8 * sum_j exp(-|x_i-x_j|/3) * (x_i - x_j)
// Symmetric (Newton's-3rd-law) formulation: each unordered pair computed once,
// -F routed to the column owner via warp shuffles; partial sums delivered with
// atomicAdd onto a zeroed output.

#define N_PART 1024
#define NGROUP 32            // particles per group (== warp size)
#define GROUPS (N_PART / NGROUP)   // 32 groups
#define CTA_T  64            // 2 warps per CTA -> 2 groups per CTA

// -log2(e)/3 : exp(-d/3) == exp2(d * KEXP)
#define KEXP  (-0.48089834696298783f)
#define ETA_S (0.8f)

__device__ __forceinline__ float fast_sqrt(float x) {
    float r; asm("sqrt.approx.f32 %0, %1;" : "=f"(r) : "f"(x)); return r;
}
__device__ __forceinline__ float fast_ex2(float x) {
    float r; asm("ex2.approx.f32 %0, %1;" : "=f"(r) : "f"(x)); return r;
}

__global__ void zero_kernel(float* __restrict__ out, int n) {
    int idx = blockIdx.x * blockDim.x + threadIdx.x;
    int stride = gridDim.x * blockDim.x;
    for (int k = idx; k < n; k += stride) out[k] = 0.0f;
}

__global__ __launch_bounds__(CTA_T) void backflow_sym_kernel(
    const float* __restrict__ x, float* __restrict__ out)
{
    __shared__ float4 s[N_PART];   // 16 KB: {x,y,z,pad} per particle

    const int b   = blockIdx.y;
    const int tid = threadIdx.x;

    const float* __restrict__ xb = x + (size_t)b * (N_PART * 3);

    // Cooperative coalesced load, de-interleave into float4 SoA-ish layout.
    #pragma unroll
    for (int k = tid; k < 3 * N_PART; k += CTA_T) {
        float v = xb[k];
        int p = k / 3;
        int c = k - 3 * p;
        reinterpret_cast<float*>(&s[p])[c] = v;
    }
    __syncthreads();

    const int warp = tid >> 5;
    const int lane = tid & 31;
    const int g    = (blockIdx.x << 1) + warp;   // group id 0..31
    const int Ib   = g << 5;                     // row base

    const float4 me = s[Ib + lane];
    const float xi = me.x, yi = me.y, zi = me.z;

    float aAx = 0.f, aAy = 0.f, aAz = 0.f;

    // ---- diagonal tile (non-symmetric; j==i term is exactly 0) ----
    #pragma unroll 4
    for (int k = 0; k < NGROUP; ++k) {
        int j = Ib + ((lane + k) & 31);
        float4 o = s[j];
        float dx = xi - o.x, dy = yi - o.y, dz = zi - o.z;
        float d2 = fmaf(dx, dx, fmaf(dy, dy, dz * dz));
        float e  = fast_ex2(fast_sqrt(d2) * KEXP);
        aAx = fmaf(e, dx, aAx);
        aAy = fmaf(e, dy, aAy);
        aAz = fmaf(e, dz, aAz);
    }

    // ---- symmetric tiles: column groups g+1 .. g+15 (mod 32), +g+16 for g<16 ----
    const int ntiles = (g < (GROUPS / 2)) ? (GROUPS / 2) : (GROUPS / 2 - 1);

    for (int t = 1; t <= ntiles; ++t) {
        const int Jb = (((g + t) & (GROUPS - 1)) << 5);

        float bx = 0.f, by = 0.f, bz = 0.f;   // column accumulator (for j = Jb + lane)

        #pragma unroll 4
        for (int k = 0; k < NGROUP; ++k) {
            int j = Jb + ((lane + k) & 31);
            float4 o = s[j];
            float dx = xi - o.x, dy = yi - o.y, dz = zi - o.z;
            float d2 = fmaf(dx, dx, fmaf(dy, dy, dz * dz));
            float e  = fast_ex2(fast_sqrt(d2) * KEXP);
            float Fx = e * dx, Fy = e * dy, Fz = e * dz;
            aAx += Fx; aAy += Fy; aAz += Fz;
            // route -F to the lane owning this column: lane c takes F from lane (c-k)&31
            int src = (lane - k) & 31;
            bx -= __shfl_sync(0xffffffffu, Fx, src);
            by -= __shfl_sync(0xffffffffu, Fy, src);
            bz -= __shfl_sync(0xffffffffu, Fz, src);
        }

        float* oj = out + ((size_t)b * N_PART + Jb + lane) * 3;
        atomicAdd(oj + 0, ETA_S * bx);
        atomicAdd(oj + 1, ETA_S * by);
        atomicAdd(oj + 2, ETA_S * bz);
    }

    // ---- deliver row sums ----
    float* oi = out + ((size_t)b * N_PART + Ib + lane) * 3;
    atomicAdd(oi + 0, ETA_S * aAx);
    atomicAdd(oi + 1, ETA_S * aAy);
    atomicAdd(oi + 2, ETA_S * aAz);
}

extern "C" void kernel_launch(void* const* d_in, const int* in_sizes, int n_in,
                              void* d_out, int out_size)
{
    const float* x = (const float*)d_in[0];
    float* out = (float*)d_out;

    int B = in_sizes[0] / (N_PART * 3);
    if (B < 1) B = 1;

    zero_kernel<<<256, 512>>>(out, out_size);

    dim3 grid(GROUPS / 2, B);   // (16, B) = 1024 CTAs for B=64
    dim3 block(CTA_T);
    backflow_sym_kernel<<<grid, block>>>(x, out);
}